// round 14
// baseline (speedup 1.0000x reference)
#include <cuda_runtime.h>
#include <cuda_fp16.h>
#include <cstdint>

#define BQ 1024
#define TT 365
#define DD 5
#define SS 27
#define HH 256
#define WROW (DD + HH)

#define BT   64          // batch rows per group (MMA M)
#define NGC  96          // gate cols per CTA (MMA N)
#define GROUPS 16
#define CPG    8
#define NCTA 128
#define NTHR 512

#define LO_SCALE 2048.0f
#define LO_INV   (1.0f / 2048.0f)

// SMEM layout (bytes). ROWB = 560 = 35*16 (odd 16B stride -> conflict-free ldmatrix)
#define ROWB 560
#define OFF_XS  0                       // [2][64][5] float   2560
#define OFF_AHI 2560                    // 64 x 560           35840
#define OFF_ALO 38400
#define OFF_BHI 74240                   // 96 x 560           53760
#define OFF_BLO 128000
#define SMEM_SZ 181760

__device__ __half   g_hhi[2][BQ][HH];
__device__ __half   g_hlo[2][BQ][HH];
__device__ unsigned g_flag[GROUPS * CPG * 32];
__device__ unsigned g_done[GROUPS * 32];

__device__ __forceinline__ uint32_t s2u(const void* p) {
    uint32_t a;
    asm("{ .reg .u64 t; cvta.to.shared.u64 t, %1; cvt.u32.u64 %0, t; }" : "=r"(a) : "l"(p));
    return a;
}
__device__ __forceinline__ float sigmoidf_(float x) {
    return __fdividef(1.f, 1.f + __expf(-x));
}
__device__ __forceinline__ float tanhf_(float x) {
    float e = __expf(-2.f * fabsf(x));
    return copysignf(__fdividef(1.f - e, 1.f + e), x);
}
__device__ __forceinline__ void ldsm4(uint32_t& r0, uint32_t& r1, uint32_t& r2, uint32_t& r3,
                                      uint32_t a) {
    asm volatile("ldmatrix.sync.aligned.m8n8.x4.shared.b16 {%0,%1,%2,%3}, [%4];"
                 : "=r"(r0), "=r"(r1), "=r"(r2), "=r"(r3) : "r"(a));
}
__device__ __forceinline__ void ldsm2(uint32_t& r0, uint32_t& r1, uint32_t a) {
    asm volatile("ldmatrix.sync.aligned.m8n8.x2.shared.b16 {%0,%1}, [%2];"
                 : "=r"(r0), "=r"(r1) : "r"(a));
}
__device__ __forceinline__ void mma16816(float* d, uint32_t a0, uint32_t a1, uint32_t a2,
                                         uint32_t a3, uint32_t b0, uint32_t b1) {
    asm volatile(
        "mma.sync.aligned.m16n8k16.row.col.f32.f16.f16.f32 "
        "{%0,%1,%2,%3}, {%4,%5,%6,%7}, {%8,%9}, {%0,%1,%2,%3};"
        : "+f"(d[0]), "+f"(d[1]), "+f"(d[2]), "+f"(d[3])
        : "r"(a0), "r"(a1), "r"(a2), "r"(a3), "r"(b0), "r"(b1));
}
__device__ __forceinline__ void cpa16(uint32_t dst, const void* src) {
    asm volatile("cp.async.cg.shared.global [%0], [%1], 16;" :: "r"(dst), "l"(src) : "memory");
}
__device__ __forceinline__ void cpa4(uint32_t dst, const void* src) {
    asm volatile("cp.async.ca.shared.global [%0], [%1], 4;" :: "r"(dst), "l"(src) : "memory");
}

// Gate-interleaved N permutation for 24-col warp tiles.
// Physical B row n: cgq=n/24, r=n%24, p=r>>3 (n8 tile), tig=(r&7)>>1, b=r&1.
// Slot s=2p+b -> gate=s%3, h-col = cgq*8 + tig*2 + s/3  (per-CTA local).
__device__ __forceinline__ int n2map(int n, int* gate) {
    const int cgq = n / 24, r = n % 24;
    const int p = r >> 3, tig = (r & 7) >> 1, b = r & 1;
    const int s = 2 * p + b;
    *gate = s % 3;
    return cgq * 8 + tig * 2 + s / 3;
}

__global__ __launch_bounds__(NTHR, 1)
void ealstm_kernel(const float* __restrict__ x_dyn,  const float* __restrict__ x_stat,
                   const float* __restrict__ W_i,    const float* __restrict__ b_i,
                   const float* __restrict__ W_f,    const float* __restrict__ b_f,
                   const float* __restrict__ W_g,    const float* __restrict__ b_g,
                   const float* __restrict__ W_o,    const float* __restrict__ b_o,
                   const float* __restrict__ W_head, const float* __restrict__ b_head,
                   float* __restrict__ out)
{
    extern __shared__ char smem[];
    const int tid  = threadIdx.x;
    const int wid  = tid >> 5;
    const int lane = tid & 31;
    const int bi   = blockIdx.x >> 3;
    const int cj   = blockIdx.x & 7;
    const int row0 = bi * BT;
    const int col0 = cj * 32;

    float* xs = (float*)(smem + OFF_XS);
    const uint32_t sXS  = s2u(smem + OFF_XS);
    const uint32_t sAHI = s2u(smem + OFF_AHI);
    const uint32_t sALO = s2u(smem + OFF_ALO);
    const uint32_t sBHI = s2u(smem + OFF_BHI);
    const uint32_t sBLO = s2u(smem + OFF_BLO);

    // ---- one-time: zero A and B tiles ----
    for (int e = tid; e < (BT * ROWB) / 16; e += NTHR) {
        *(uint4*)(smem + OFF_AHI + e * 16) = make_uint4(0, 0, 0, 0);
        *(uint4*)(smem + OFF_ALO + e * 16) = make_uint4(0, 0, 0, 0);
    }
    for (int e = tid; e < (NGC * ROWB) / 16; e += NTHR) {
        *(uint4*)(smem + OFF_BHI + e * 16) = make_uint4(0, 0, 0, 0);
        *(uint4*)(smem + OFF_BLO + e * 16) = make_uint4(0, 0, 0, 0);
    }
    __syncthreads();

    // ---- B tiles: recurrent weights (k 0..255), gate-interleaved n ----
    for (int e = tid; e < NGC * HH; e += NTHR) {
        const int n = e >> 8, k = e & 255;
        int gate;
        const int col = col0 + n2map(n, &gate);
        const float* W = gate == 0 ? W_f : (gate == 1 ? W_g : W_o);
        const float w = __ldg(&W[col * WROW + DD + k]);
        const __half whi = __float2half_rn(w);
        const __half wlo = __float2half_rn((w - __half2float(whi)) * LO_SCALE);
        *(__half*)(smem + OFF_BHI + n * ROWB + k * 2) = whi;
        *(__half*)(smem + OFF_BLO + n * ROWB + k * 2) = wlo;
    }
    // B x-region: k 256..260 = wx, k 261 = bias
    if (tid < NGC) {
        const int n = tid;
        int gate;
        const int col = col0 + n2map(n, &gate);
        const float* W = gate == 0 ? W_f : (gate == 1 ? W_g : W_o);
        const float* b = gate == 0 ? b_f : (gate == 1 ? b_g : b_o);
        for (int kk = 0; kk < 6; kk++) {
            const float v = kk < DD ? __ldg(&W[col * WROW + kk]) : __ldg(&b[col]);
            const __half vh = __float2half_rn(v);
            const __half vl = __float2half_rn((v - __half2float(vh)) * LO_SCALE);
            *(__half*)(smem + OFF_BHI + n * ROWB + (256 + kk) * 2) = vh;
            *(__half*)(smem + OFF_BLO + n * ROWB + (256 + kk) * 2) = vl;
        }
    }
    if (tid < BT)
        *(__half*)(smem + OFF_AHI + tid * ROWB + 261 * 2) = __float2half_rn(1.0f);
    if (tid < BT) {
        const float* xp = x_dyn + (size_t)(row0 + tid) * TT * DD;
#pragma unroll
        for (int d = 0; d < DD; d++) xs[tid * DD + d] = __ldg(xp + d);
    }

    // ---- MMA warp geometry: 16 warps = 4 row-groups x 4 col-groups (24 cols) ----
    const int rg  = wid >> 2;               // rows [rg*16, +16)
    const int cgq = wid & 3;                // cols [cgq*24, +24)
    const int tg  = lane >> 2;
    const int tig = lane & 3;

    const uint32_t aOff = (uint32_t)((rg * 16 + (lane & 15)) * ROWB + (lane >> 4) * 16);
    const uint32_t aHiA = sAHI + aOff;
    const uint32_t aLoA = sALO + aOff;
    // B x4 (tiles p=0,1: 16 rows) and x2 (tile p=2: 8 rows)
    const uint32_t b4Off =
        (uint32_t)((cgq * 24 + ((lane >> 4) * 8) + (lane & 7)) * ROWB +
                   ((lane & 8) ? 16 : 0));
    const uint32_t b2Off =
        (uint32_t)((cgq * 24 + 16 + (lane & 7)) * ROWB + (((lane >> 3) & 1) ? 16 : 0));
    const uint32_t bHiA4 = sBHI + b4Off, bLoA4 = sBLO + b4Off;
    const uint32_t bHiA2 = sBHI + b2Off, bLoA2 = sBLO + b2Off;

    // ---- per-lane cell state: rows {er0, er0+8}, cols {ecb, ecb+1} (global) ----
    const int er0 = rg * 16 + tg;
    const int ecb = col0 + cgq * 8 + tig * 2;
    float ig[4], cs[4];
#pragma unroll
    for (int z = 0; z < 2; z++)
#pragma unroll
        for (int a = 0; a < 2; a++) {
            const int r = row0 + er0 + z * 8;
            const int c = ecb + a;
            float s = __ldg(&b_i[c]);
            for (int ss = 0; ss < SS; ss++)
                s = fmaf(__ldg(&x_stat[r * SS + ss]), __ldg(&W_i[c * SS + ss]), s);
            ig[z * 2 + a] = sigmoidf_(s);
            cs[z * 2 + a] = 0.f;
        }
    __syncthreads();

    const int ks0 = 2 * cj, ks1 = 2 * cj + 1;    // own k-steps (self-staged)
    const int ubase = cj << 2;                   // own 16B-units per row

    // ---- recurrence ----
    for (int t = 0; t < TT; t++) {
        // x(t) -> A x-region (hi/lo)
        if (tid < BT) {
            const float* xr = xs + (t & 1) * 320 + tid * DD;
#pragma unroll
            for (int d = 0; d < DD; d++) {
                const float v = xr[d];
                const __half vh = __float2half_rn(v);
                const __half vl = __float2half_rn((v - __half2float(vh)) * LO_SCALE);
                *(__half*)(smem + OFF_AHI + tid * ROWB + (256 + d) * 2) = vh;
                *(__half*)(smem + OFF_ALO + tid * ROWB + (256 + d) * 2) = vl;
            }
        }
        if (t > 0 && tid < CPG) {
            const volatile unsigned* fp = &g_flag[(bi * CPG + tid) * 32];
            while (*fp < (unsigned)t) __nanosleep(32);
        }
        __syncthreads();

        // stage 7 peer chunks (28 of 32 16B-units per row) + x(t+1) prefetch
        if (t > 0) {
            const int rb = (t - 1) & 1;
            for (int e = tid; e < 1792; e += NTHR) {
                const int r = e / 28, u = e - r * 28;
                const int unit = u + (u >= ubase ? 4 : 0);
                const uint32_t d = (uint32_t)(r * ROWB + unit * 16);
                cpa16(sAHI + d, (const char*)&g_hhi[rb][row0 + r][0] + unit * 16);
                cpa16(sALO + d, (const char*)&g_hlo[rb][row0 + r][0] + unit * 16);
            }
        }
        {
            const int tn = (t + 1 < TT) ? t + 1 : TT - 1;
            const uint32_t xb = sXS + (uint32_t)(((t + 1) & 1) * 320 * 4);
            for (int e = tid; e < BT * DD; e += NTHR) {
                const int r = e / DD, d = e - r * DD;
                cpa4(xb + (uint32_t)e * 4, &x_dyn[((size_t)(row0 + r) * TT + tn) * DD + d]);
            }
        }
        asm volatile("cp.async.commit_group;" ::: "memory");

        float d1[3][4], d2[3][4];
#pragma unroll
        for (int q = 0; q < 3; q++)
#pragma unroll
            for (int v = 0; v < 4; v++) { d1[q][v] = 0.f; d2[q][v] = 0.f; }

#define DO_KSTEP(KS)                                                                   \
        {                                                                              \
            const uint32_t kb = (uint32_t)((KS) * 32);                                 \
            uint32_t ah0, ah1, ah2, ah3, al0, al1, al2, al3;                           \
            ldsm4(ah0, ah1, ah2, ah3, aHiA + kb);                                      \
            ldsm4(al0, al1, al2, al3, aLoA + kb);                                      \
            uint32_t bh0, bh1, bh2, bh3, bh4, bh5;                                     \
            uint32_t bl0, bl1, bl2, bl3, bl4, bl5;                                     \
            ldsm4(bh0, bh1, bh2, bh3, bHiA4 + kb);                                     \
            ldsm2(bh4, bh5, bHiA2 + kb);                                               \
            ldsm4(bl0, bl1, bl2, bl3, bLoA4 + kb);                                     \
            ldsm2(bl4, bl5, bLoA2 + kb);                                               \
            mma16816(d1[0], ah0, ah1, ah2, ah3, bh0, bh1);                             \
            mma16816(d1[1], ah0, ah1, ah2, ah3, bh2, bh3);                             \
            mma16816(d1[2], ah0, ah1, ah2, ah3, bh4, bh5);                             \
            mma16816(d2[0], ah0, ah1, ah2, ah3, bl0, bl1);                             \
            mma16816(d2[1], ah0, ah1, ah2, ah3, bl2, bl3);                             \
            mma16816(d2[2], ah0, ah1, ah2, ah3, bl4, bl5);                             \
            mma16816(d2[0], al0, al1, al2, al3, bh0, bh1);                             \
            mma16816(d2[1], al0, al1, al2, al3, bh2, bh3);                             \
            mma16816(d2[2], al0, al1, al2, al3, bh4, bh5);                             \
        }

        // overlap the cp.async flight with x k-step + own two k-steps (self-staged)
        DO_KSTEP(16);
        DO_KSTEP(ks0);
        DO_KSTEP(ks1);
        asm volatile("cp.async.wait_group 0;" ::: "memory");
        __syncthreads();
#pragma unroll
        for (int ks = 0; ks < 16; ks++) {
            if ((ks >> 1) == cj) continue;       // own k-steps already done
            DO_KSTEP(ks);
        }

        // ---- in-register epilogue; publish h to global AND own SMEM A chunk ----
        // cell (z,a): slots s=3a+{0,1,2} -> tile p=s>>1, col b=s&1, elem (z<<1)|b
        const int wb = t & 1;
        __half hh[2][2], hl[2][2];
#pragma unroll
        for (int z = 0; z < 2; z++)
#pragma unroll
            for (int a = 0; a < 2; a++) {
                const int sf = 3 * a, sg = 3 * a + 1, so = 3 * a + 2;
                const float pf = fmaf(d2[sf >> 1][(z << 1) | (sf & 1)], LO_INV,
                                      d1[sf >> 1][(z << 1) | (sf & 1)]);
                const float pg = fmaf(d2[sg >> 1][(z << 1) | (sg & 1)], LO_INV,
                                      d1[sg >> 1][(z << 1) | (sg & 1)]);
                const float po = fmaf(d2[so >> 1][(z << 1) | (so & 1)], LO_INV,
                                      d1[so >> 1][(z << 1) | (so & 1)]);
                const float f = sigmoidf_(pf);
                const float g = tanhf_(pg);
                const float o = sigmoidf_(po);
                const float cn = fmaf(f, cs[z * 2 + a], ig[z * 2 + a] * g);
                cs[z * 2 + a] = cn;
                const float hv = o * tanhf_(cn);
                hh[z][a] = __float2half_rn(hv);
                hl[z][a] = __float2half_rn((hv - __half2float(hh[z][a])) * LO_SCALE);
            }
        *(uint32_t*)&g_hhi[wb][row0 + er0][ecb]     = *(uint32_t*)hh[0];
        *(uint32_t*)&g_hhi[wb][row0 + er0 + 8][ecb] = *(uint32_t*)hh[1];
        *(uint32_t*)&g_hlo[wb][row0 + er0][ecb]     = *(uint32_t*)hl[0];
        *(uint32_t*)&g_hlo[wb][row0 + er0 + 8][ecb] = *(uint32_t*)hl[1];
        // self-stage own chunk for next step (skips the global round-trip)
        *(uint32_t*)(smem + OFF_AHI + er0 * ROWB + ecb * 2)       = *(uint32_t*)hh[0];
        *(uint32_t*)(smem + OFF_AHI + (er0 + 8) * ROWB + ecb * 2) = *(uint32_t*)hh[1];
        *(uint32_t*)(smem + OFF_ALO + er0 * ROWB + ecb * 2)       = *(uint32_t*)hl[0];
        *(uint32_t*)(smem + OFF_ALO + (er0 + 8) * ROWB + ecb * 2) = *(uint32_t*)hl[1];

        __syncthreads();
        if (tid == 0) {
            __threadfence();                     // cumulative: covers all CTA stores
            atomicAdd(&g_flag[(bi * CPG + cj) * 32], 1u);
        }
    }

    // ---- head (cj == 0): out[b] = h_T . W_head + b_head ----
    if (cj == 0) {
        if (tid < CPG) {
            const volatile unsigned* fp = &g_flag[(bi * CPG + tid) * 32];
            while (*fp < (unsigned)TT) __nanosleep(32);
        }
        __syncthreads();
        if (tid < 256) {
            const int row = tid >> 2, part = tid & 3;
            const int r = row0 + row;
            const int rb = (TT - 1) & 1;
            float s = 0.f;
            for (int k = part * 64; k < part * 64 + 64; k++) {
                const float hv = __half2float(__ldcg(&g_hhi[rb][r][k])) +
                                 __half2float(__ldcg(&g_hlo[rb][r][k])) * LO_INV;
                s = fmaf(hv, __ldg(&W_head[k]), s);
            }
            s += __shfl_xor_sync(0xffffffffu, s, 1);
            s += __shfl_xor_sync(0xffffffffu, s, 2);
            if (part == 0) out[r] = s + __ldg(&b_head[0]);
        }
    }

    // ---- reset flags for deterministic graph replay ----
    __syncthreads();
    if (tid == 0) {
        __threadfence();
        atomicAdd(&g_done[bi * 32], 1u);
        if (cj == 0) {
            while (atomicAdd(&g_done[bi * 32], 0u) < CPG) __nanosleep(64);
            for (int s = 0; s < CPG; s++)
                atomicExch(&g_flag[(bi * CPG + s) * 32], 0u);
            atomicExch(&g_done[bi * 32], 0u);
        }
    }
}

extern "C" void kernel_launch(void* const* d_in, const int* in_sizes, int n_in,
                              void* d_out, int out_size) {
    (void)in_sizes; (void)n_in; (void)out_size;
    cudaFuncSetAttribute(ealstm_kernel,
                         cudaFuncAttributeMaxDynamicSharedMemorySize, SMEM_SZ);
    ealstm_kernel<<<NCTA, NTHR, SMEM_SZ>>>(
        (const float*)d_in[0],  (const float*)d_in[1],
        (const float*)d_in[2],  (const float*)d_in[3],
        (const float*)d_in[4],  (const float*)d_in[5],
        (const float*)d_in[6],  (const float*)d_in[7],
        (const float*)d_in[8],  (const float*)d_in[9],
        (const float*)d_in[10], (const float*)d_in[11],
        (float*)d_out);
}

// round 15
// speedup vs baseline: 1.3297x; 1.3297x over previous
#include <cuda_runtime.h>
#include <cuda_fp16.h>
#include <cstdint>

#define BQ 1024
#define TT 365
#define DD 5
#define SS 27
#define HH 256
#define WROW (DD + HH)

#define BT   64          // batch rows per group (MMA M)
#define NGC  96          // gate cols per CTA (MMA N)
#define GROUPS 16
#define CPG    8
#define NCTA 128
#define NTHR 256

#define LO_SCALE 2048.0f
#define LO_INV   (1.0f / 2048.0f)

// SMEM layout (bytes). ROWB = 560 = 35*16 (odd 16B stride -> conflict-free ldmatrix)
#define ROWB 560
#define OFF_XS  0                       // [2][64][5] float   2560
#define OFF_AHI 2560                    // 64 x 560           35840
#define OFF_ALO 38400
#define OFF_BHI 74240                   // 96 x 560           53760
#define SMEM_SZ 128000

__device__ __half   g_hhi[2][BQ][HH];
__device__ __half   g_hlo[2][BQ][HH];
__device__ unsigned g_flag[GROUPS * CPG * 32];
__device__ unsigned g_done[GROUPS * 32];

__device__ __forceinline__ uint32_t s2u(const void* p) {
    uint32_t a;
    asm("{ .reg .u64 t; cvta.to.shared.u64 t, %1; cvt.u32.u64 %0, t; }" : "=r"(a) : "l"(p));
    return a;
}
__device__ __forceinline__ float sigmoidf_(float x) {
    return __fdividef(1.f, 1.f + __expf(-x));
}
__device__ __forceinline__ float tanhf_(float x) {
    float e = __expf(-2.f * fabsf(x));
    return copysignf(__fdividef(1.f - e, 1.f + e), x);
}
__device__ __forceinline__ void ldsm4(uint32_t& r0, uint32_t& r1, uint32_t& r2, uint32_t& r3,
                                      uint32_t a) {
    asm volatile("ldmatrix.sync.aligned.m8n8.x4.shared.b16 {%0,%1,%2,%3}, [%4];"
                 : "=r"(r0), "=r"(r1), "=r"(r2), "=r"(r3) : "r"(a));
}
__device__ __forceinline__ void mma16816(float* d, uint32_t a0, uint32_t a1, uint32_t a2,
                                         uint32_t a3, uint32_t b0, uint32_t b1) {
    asm volatile(
        "mma.sync.aligned.m16n8k16.row.col.f32.f16.f16.f32 "
        "{%0,%1,%2,%3}, {%4,%5,%6,%7}, {%8,%9}, {%0,%1,%2,%3};"
        : "+f"(d[0]), "+f"(d[1]), "+f"(d[2]), "+f"(d[3])
        : "r"(a0), "r"(a1), "r"(a2), "r"(a3), "r"(b0), "r"(b1));
}
__device__ __forceinline__ void cpa16(uint32_t dst, const void* src) {
    asm volatile("cp.async.cg.shared.global [%0], [%1], 16;" :: "r"(dst), "l"(src) : "memory");
}
__device__ __forceinline__ void cpa4(uint32_t dst, const void* src) {
    asm volatile("cp.async.ca.shared.global [%0], [%1], 4;" :: "r"(dst), "l"(src) : "memory");
}

// Gate-interleaved N permutation: physical B row n -> (gate, h-col).
__device__ __forceinline__ int n2map(int n, int* gate) {
    const int cg = n / 48, r = n % 48;
    const int q = r >> 3, tig = (r & 7) >> 1, p = r & 1;
    const int s = 2 * q + p;
    *gate = s % 3;
    return cg * 16 + tig * 4 + s / 3;
}

__global__ __launch_bounds__(NTHR, 1)
void ealstm_kernel(const float* __restrict__ x_dyn,  const float* __restrict__ x_stat,
                   const float* __restrict__ W_i,    const float* __restrict__ b_i,
                   const float* __restrict__ W_f,    const float* __restrict__ b_f,
                   const float* __restrict__ W_g,    const float* __restrict__ b_g,
                   const float* __restrict__ W_o,    const float* __restrict__ b_o,
                   const float* __restrict__ W_head, const float* __restrict__ b_head,
                   float* __restrict__ out)
{
    extern __shared__ char smem[];
    const int tid  = threadIdx.x;
    const int wid  = tid >> 5;
    const int lane = tid & 31;
    const int bi   = blockIdx.x >> 3;
    const int cj   = blockIdx.x & 7;
    const int row0 = bi * BT;
    const int col0 = cj * 32;

    float* xs = (float*)(smem + OFF_XS);
    const uint32_t sXS  = s2u(smem + OFF_XS);
    const uint32_t sAHI = s2u(smem + OFF_AHI);
    const uint32_t sALO = s2u(smem + OFF_ALO);
    const uint32_t sBHI = s2u(smem + OFF_BHI);

    // ---- one-time: zero A and B tiles ----
    for (int e = tid; e < (BT * ROWB) / 16; e += NTHR) {
        *(uint4*)(smem + OFF_AHI + e * 16) = make_uint4(0, 0, 0, 0);
        *(uint4*)(smem + OFF_ALO + e * 16) = make_uint4(0, 0, 0, 0);
    }
    for (int e = tid; e < (NGC * ROWB) / 16; e += NTHR)
        *(uint4*)(smem + OFF_BHI + e * 16) = make_uint4(0, 0, 0, 0);
    __syncthreads();

    // ---- B tile: recurrent weights (k 0..255), single fp16, gate-interleaved n ----
    for (int e = tid; e < NGC * HH; e += NTHR) {
        const int n = e >> 8, k = e & 255;
        int gate;
        const int col = col0 + n2map(n, &gate);
        const float* W = gate == 0 ? W_f : (gate == 1 ? W_g : W_o);
        *(__half*)(smem + OFF_BHI + n * ROWB + k * 2) =
            __float2half_rn(__ldg(&W[col * WROW + DD + k]));
    }
    // B x-region: k 256..260 = wx, k 261 = bias
    if (tid < NGC) {
        const int n = tid;
        int gate;
        const int col = col0 + n2map(n, &gate);
        const float* W = gate == 0 ? W_f : (gate == 1 ? W_g : W_o);
        const float* b = gate == 0 ? b_f : (gate == 1 ? b_g : b_o);
        for (int kk = 0; kk < 6; kk++) {
            const float v = kk < DD ? __ldg(&W[col * WROW + kk]) : __ldg(&b[col]);
            *(__half*)(smem + OFF_BHI + n * ROWB + (256 + kk) * 2) = __float2half_rn(v);
        }
    }
    if (tid < BT)
        *(__half*)(smem + OFF_AHI + tid * ROWB + 261 * 2) = __float2half_rn(1.0f);
    if (tid < BT) {
        const float* xp = x_dyn + (size_t)(row0 + tid) * TT * DD;
#pragma unroll
        for (int d = 0; d < DD; d++) xs[tid * DD + d] = __ldg(xp + d);
    }

    // ---- MMA warp geometry: 8 warps = 4 row-groups x 2 col-groups (48 cols) ----
    const int rg  = wid >> 1;
    const int cg  = wid & 1;
    const int tg  = lane >> 2;
    const int tig = lane & 3;

    const uint32_t aOff = (uint32_t)((rg * 16 + (lane & 15)) * ROWB + (lane >> 4) * 16);
    const uint32_t aHiA = sAHI + aOff;
    const uint32_t aLoA = sALO + aOff;
    uint32_t bHiA[3];
#pragma unroll
    for (int p = 0; p < 3; p++) {
        const uint32_t bOff =
            (uint32_t)((cg * 48 + p * 16 + ((lane >> 4) * 8) + (lane & 7)) * ROWB +
                       ((lane & 8) ? 16 : 0));
        bHiA[p] = sBHI + bOff;
    }

    // ---- per-lane cell state: rows {er0, er0+8}, cols {ecb..ecb+3} (global) ----
    const int er0 = rg * 16 + tg;
    const int ecb = col0 + cg * 16 + tig * 4;
    float ig[8], cs[8];
#pragma unroll
    for (int z = 0; z < 2; z++)
#pragma unroll
        for (int a = 0; a < 4; a++) {
            const int r = row0 + er0 + z * 8;
            const int c = ecb + a;
            float s = __ldg(&b_i[c]);
            for (int ss = 0; ss < SS; ss++)
                s = fmaf(__ldg(&x_stat[r * SS + ss]), __ldg(&W_i[c * SS + ss]), s);
            ig[z * 4 + a] = sigmoidf_(s);
            cs[z * 4 + a] = 0.f;
        }
    __syncthreads();

    const int ks0 = 2 * cj, ks1 = 2 * cj + 1;    // own k-steps (self-staged)

    // ---- recurrence ----
    for (int t = 0; t < TT; t++) {
        // x(t) -> A x-region (hi/lo)
        if (tid < BT) {
            const float* xr = xs + (t & 1) * 320 + tid * DD;
#pragma unroll
            for (int d = 0; d < DD; d++) {
                const float v = xr[d];
                const __half vh = __float2half_rn(v);
                const __half vl = __float2half_rn((v - __half2float(vh)) * LO_SCALE);
                *(__half*)(smem + OFF_AHI + tid * ROWB + (256 + d) * 2) = vh;
                *(__half*)(smem + OFF_ALO + tid * ROWB + (256 + d) * 2) = vl;
            }
        }

        // ---- per-warp producer pipelining: warp w polls flag w, stages chunk w ----
        if (t > 0) {
            const int rb = (t - 1) & 1;
            if (wid != cj) {
                if (lane == 0) {
                    const volatile unsigned* fp = &g_flag[(bi * CPG + wid) * 32];
                    while (*fp < (unsigned)t) {}
                }
                __syncwarp();
#pragma unroll
                for (int i = 0; i < 8; i++) {
                    const int e = lane + 32 * i;          // 0..255
                    const int r = e >> 2, u = e & 3;
                    const int unit = (wid << 2) + u;
                    const uint32_t d = (uint32_t)(r * ROWB + unit * 16);
                    cpa16(sAHI + d, (const char*)&g_hhi[rb][row0 + r][0] + unit * 16);
                    cpa16(sALO + d, (const char*)&g_hlo[rb][row0 + r][0] + unit * 16);
                }
            } else {
                // own chunk is self-staged; this warp prefetches x(t+1)
                const int tn = (t + 1 < TT) ? t + 1 : TT - 1;
                const uint32_t xb = sXS + (uint32_t)(((t + 1) & 1) * 320 * 4);
#pragma unroll
                for (int i = 0; i < 10; i++) {
                    const int e = lane + 32 * i;          // 0..319
                    const int r = e / 5, d = e - r * 5;
                    cpa4(xb + (uint32_t)e * 4,
                         &x_dyn[((size_t)(row0 + r) * TT + tn) * DD + d]);
                }
            }
            asm volatile("cp.async.commit_group;" ::: "memory");
        } else {
            const uint32_t xb = sXS + (uint32_t)(320 * 4);
            for (int e = tid; e < BT * DD; e += NTHR) {
                const int r = e / DD, d = e - r * DD;
                cpa4(xb + (uint32_t)e * 4, &x_dyn[((size_t)(row0 + r) * TT + 1) * DD + d]);
            }
            asm volatile("cp.async.commit_group;" ::: "memory");
        }
        __syncthreads();                                  // x-region visible

        float d1[6][4], d2[6][4];
#pragma unroll
        for (int q = 0; q < 6; q++)
#pragma unroll
            for (int v = 0; v < 4; v++) { d1[q][v] = 0.f; d2[q][v] = 0.f; }

#define DO_KSTEP(KS)                                                                   \
        {                                                                              \
            const uint32_t kb = (uint32_t)((KS) * 32);                                 \
            uint32_t ah0, ah1, ah2, ah3, al0, al1, al2, al3;                           \
            ldsm4(ah0, ah1, ah2, ah3, aHiA + kb);                                      \
            ldsm4(al0, al1, al2, al3, aLoA + kb);                                      \
            _Pragma("unroll")                                                          \
            for (int p = 0; p < 3; p++) {                                              \
                uint32_t bh0, bh1, bh2, bh3;                                           \
                ldsm4(bh0, bh1, bh2, bh3, bHiA[p] + kb);                               \
                mma16816(d1[p*2+0], ah0, ah1, ah2, ah3, bh0, bh1);                     \
                mma16816(d1[p*2+1], ah0, ah1, ah2, ah3, bh2, bh3);                     \
                mma16816(d2[p*2+0], al0, al1, al2, al3, bh0, bh1);                     \
                mma16816(d2[p*2+1], al0, al1, al2, al3, bh2, bh3);                     \
            }                                                                          \
        }

        // overlap the cp.async flight with x k-step + own two k-steps (self-staged)
        DO_KSTEP(16);
        DO_KSTEP(ks0);
        DO_KSTEP(ks1);
        asm volatile("cp.async.wait_group 0;" ::: "memory");
        __syncthreads();
#pragma unroll
        for (int ks = 0; ks < 16; ks++) {
            if ((ks >> 1) == cj) continue;       // own k-steps already done
            DO_KSTEP(ks);
        }

        // ---- in-register epilogue; publish h to global AND own SMEM A chunk ----
        const int wb = t & 1;
        __half hh[2][4], hl[2][4];
#pragma unroll
        for (int z = 0; z < 2; z++)
#pragma unroll
            for (int a = 0; a < 4; a++) {
                const int sf = 3 * a, sg = 3 * a + 1, so = 3 * a + 2;
                const float pf = fmaf(d2[sf >> 1][(z << 1) | (sf & 1)], LO_INV,
                                      d1[sf >> 1][(z << 1) | (sf & 1)]);
                const float pg = fmaf(d2[sg >> 1][(z << 1) | (sg & 1)], LO_INV,
                                      d1[sg >> 1][(z << 1) | (sg & 1)]);
                const float po = fmaf(d2[so >> 1][(z << 1) | (so & 1)], LO_INV,
                                      d1[so >> 1][(z << 1) | (so & 1)]);
                const float f = sigmoidf_(pf);
                const float g = tanhf_(pg);
                const float o = sigmoidf_(po);
                const float cn = fmaf(f, cs[z * 4 + a], ig[z * 4 + a] * g);
                cs[z * 4 + a] = cn;
                const float hv = o * tanhf_(cn);
                hh[z][a] = __float2half_rn(hv);
                hl[z][a] = __float2half_rn((hv - __half2float(hh[z][a])) * LO_SCALE);
            }
        *(uint2*)&g_hhi[wb][row0 + er0][ecb]     = *(uint2*)hh[0];
        *(uint2*)&g_hhi[wb][row0 + er0 + 8][ecb] = *(uint2*)hh[1];
        *(uint2*)&g_hlo[wb][row0 + er0][ecb]     = *(uint2*)hl[0];
        *(uint2*)&g_hlo[wb][row0 + er0 + 8][ecb] = *(uint2*)hl[1];
        // self-stage own chunk for next step (skips the global round-trip)
        *(uint2*)(smem + OFF_AHI + er0 * ROWB + ecb * 2)       = *(uint2*)hh[0];
        *(uint2*)(smem + OFF_AHI + (er0 + 8) * ROWB + ecb * 2) = *(uint2*)hh[1];
        *(uint2*)(smem + OFF_ALO + er0 * ROWB + ecb * 2)       = *(uint2*)hl[0];
        *(uint2*)(smem + OFF_ALO + (er0 + 8) * ROWB + ecb * 2) = *(uint2*)hl[1];

        __syncthreads();
        if (tid == 0) {
            __threadfence();                     // cumulative: covers all CTA stores
            atomicAdd(&g_flag[(bi * CPG + cj) * 32], 1u);
        }
    }

    // ---- head (cj == 0): out[b] = h_T . W_head + b_head ----
    if (cj == 0) {
        if (tid < CPG) {
            const volatile unsigned* fp = &g_flag[(bi * CPG + tid) * 32];
            while (*fp < (unsigned)TT) __nanosleep(32);
        }
        __syncthreads();
        const int row = tid >> 2, part = tid & 3;
        const int r = row0 + row;
        const int rb = (TT - 1) & 1;
        float s = 0.f;
        for (int k = part * 64; k < part * 64 + 64; k++) {
            const float hv = __half2float(__ldcg(&g_hhi[rb][r][k])) +
                             __half2float(__ldcg(&g_hlo[rb][r][k])) * LO_INV;
            s = fmaf(hv, __ldg(&W_head[k]), s);
        }
        s += __shfl_xor_sync(0xffffffffu, s, 1);
        s += __shfl_xor_sync(0xffffffffu, s, 2);
        if (part == 0) out[r] = s + __ldg(&b_head[0]);
    }

    // ---- reset flags for deterministic graph replay ----
    __syncthreads();
    if (tid == 0) {
        __threadfence();
        atomicAdd(&g_done[bi * 32], 1u);
        if (cj == 0) {
            while (atomicAdd(&g_done[bi * 32], 0u) < CPG) __nanosleep(64);
            for (int s = 0; s < CPG; s++)
                atomicExch(&g_flag[(bi * CPG + s) * 32], 0u);
            atomicExch(&g_done[bi * 32], 0u);
        }
    }
}

extern "C" void kernel_launch(void* const* d_in, const int* in_sizes, int n_in,
                              void* d_out, int out_size) {
    (void)in_sizes; (void)n_in; (void)out_size;
    cudaFuncSetAttribute(ealstm_kernel,
                         cudaFuncAttributeMaxDynamicSharedMemorySize, SMEM_SZ);
    ealstm_kernel<<<NCTA, NTHR, SMEM_SZ>>>(
        (const float*)d_in[0],  (const float*)d_in[1],
        (const float*)d_in[2],  (const float*)d_in[3],
        (const float*)d_in[4],  (const float*)d_in[5],
        (const float*)d_in[6],  (const float*)d_in[7],
        (const float*)d_in[8],  (const float*)d_in[9],
        (const float*)d_in[10], (const float*)d_in[11],
        (float*)d_out);
}

// round 16
// speedup vs baseline: 1.4021x; 1.0544x over previous
#include <cuda_runtime.h>
#include <cuda_fp16.h>
#include <cstdint>

#define BQ 1024
#define TT 365
#define DD 5
#define SS 27
#define HH 256
#define WROW (DD + HH)

#define BT   64          // batch rows per group (MMA M)
#define NGC  96          // gate cols per CTA (MMA N)
#define GROUPS 16
#define CPG    8
#define NCTA 128
#define NTHR 256

#define LO_SCALE 2048.0f
#define LO_INV   (1.0f / 2048.0f)

// SMEM layout (bytes). ROWB = 560 = 35*16 (odd 16B stride -> conflict-free ldmatrix)
#define ROWB 560
#define OFF_XS  0                       // [2][64][5] float   2560
#define OFF_AHI 2560                    // 64 x 560           35840
#define OFF_ALO 38400
#define OFF_BHI 74240                   // 96 x 560           53760
#define SMEM_SZ 128000

__device__ __half   g_hhi[2][BQ][HH];
__device__ __half   g_hlo[2][BQ][HH];
__device__ unsigned g_flag[GROUPS * CPG * 32];
__device__ unsigned g_done[GROUPS * 32];

__device__ __forceinline__ uint32_t s2u(const void* p) {
    uint32_t a;
    asm("{ .reg .u64 t; cvta.to.shared.u64 t, %1; cvt.u32.u64 %0, t; }" : "=r"(a) : "l"(p));
    return a;
}
// Precise versions (one-time i_gate init only)
__device__ __forceinline__ float sigmoid_precise(float x) {
    return __fdividef(1.f, 1.f + __expf(-x));
}
// HW tanh (sm_75+): 1 MUFU op
__device__ __forceinline__ float tanh_fast(float x) {
    float y;
    asm("tanh.approx.f32 %0, %1;" : "=f"(y) : "f"(x));
    return y;
}
__device__ __forceinline__ float sigmoid_fast(float x) {
    return fmaf(0.5f, tanh_fast(0.5f * x), 0.5f);
}
__device__ __forceinline__ void ldsm4(uint32_t& r0, uint32_t& r1, uint32_t& r2, uint32_t& r3,
                                      uint32_t a) {
    asm volatile("ldmatrix.sync.aligned.m8n8.x4.shared.b16 {%0,%1,%2,%3}, [%4];"
                 : "=r"(r0), "=r"(r1), "=r"(r2), "=r"(r3) : "r"(a));
}
__device__ __forceinline__ void mma16816(float* d, uint32_t a0, uint32_t a1, uint32_t a2,
                                         uint32_t a3, uint32_t b0, uint32_t b1) {
    asm volatile(
        "mma.sync.aligned.m16n8k16.row.col.f32.f16.f16.f32 "
        "{%0,%1,%2,%3}, {%4,%5,%6,%7}, {%8,%9}, {%0,%1,%2,%3};"
        : "+f"(d[0]), "+f"(d[1]), "+f"(d[2]), "+f"(d[3])
        : "r"(a0), "r"(a1), "r"(a2), "r"(a3), "r"(b0), "r"(b1));
}
__device__ __forceinline__ void cpa16(uint32_t dst, const void* src) {
    asm volatile("cp.async.cg.shared.global [%0], [%1], 16;" :: "r"(dst), "l"(src) : "memory");
}
__device__ __forceinline__ void cpa4(uint32_t dst, const void* src) {
    asm volatile("cp.async.ca.shared.global [%0], [%1], 4;" :: "r"(dst), "l"(src) : "memory");
}

// Gate-interleaved N permutation: physical B row n -> (gate, h-col).
__device__ __forceinline__ int n2map(int n, int* gate) {
    const int cg = n / 48, r = n % 48;
    const int q = r >> 3, tig = (r & 7) >> 1, p = r & 1;
    const int s = 2 * q + p;
    *gate = s % 3;
    return cg * 16 + tig * 4 + s / 3;
}

__global__ __launch_bounds__(NTHR, 1)
void ealstm_kernel(const float* __restrict__ x_dyn,  const float* __restrict__ x_stat,
                   const float* __restrict__ W_i,    const float* __restrict__ b_i,
                   const float* __restrict__ W_f,    const float* __restrict__ b_f,
                   const float* __restrict__ W_g,    const float* __restrict__ b_g,
                   const float* __restrict__ W_o,    const float* __restrict__ b_o,
                   const float* __restrict__ W_head, const float* __restrict__ b_head,
                   float* __restrict__ out)
{
    extern __shared__ char smem[];
    const int tid  = threadIdx.x;
    const int wid  = tid >> 5;
    const int lane = tid & 31;
    const int bi   = blockIdx.x >> 3;
    const int cj   = blockIdx.x & 7;
    const int row0 = bi * BT;
    const int col0 = cj * 32;

    float* xs = (float*)(smem + OFF_XS);
    const uint32_t sXS  = s2u(smem + OFF_XS);
    const uint32_t sAHI = s2u(smem + OFF_AHI);
    const uint32_t sALO = s2u(smem + OFF_ALO);
    const uint32_t sBHI = s2u(smem + OFF_BHI);

    // ---- one-time: zero A and B tiles ----
    for (int e = tid; e < (BT * ROWB) / 16; e += NTHR) {
        *(uint4*)(smem + OFF_AHI + e * 16) = make_uint4(0, 0, 0, 0);
        *(uint4*)(smem + OFF_ALO + e * 16) = make_uint4(0, 0, 0, 0);
    }
    for (int e = tid; e < (NGC * ROWB) / 16; e += NTHR)
        *(uint4*)(smem + OFF_BHI + e * 16) = make_uint4(0, 0, 0, 0);
    __syncthreads();

    // ---- B tile: recurrent weights (k 0..255), single fp16, gate-interleaved n ----
    for (int e = tid; e < NGC * HH; e += NTHR) {
        const int n = e >> 8, k = e & 255;
        int gate;
        const int col = col0 + n2map(n, &gate);
        const float* W = gate == 0 ? W_f : (gate == 1 ? W_g : W_o);
        *(__half*)(smem + OFF_BHI + n * ROWB + k * 2) =
            __float2half_rn(__ldg(&W[col * WROW + DD + k]));
    }
    // B x-region: k 256..260 = wx, k 261 = bias
    if (tid < NGC) {
        const int n = tid;
        int gate;
        const int col = col0 + n2map(n, &gate);
        const float* W = gate == 0 ? W_f : (gate == 1 ? W_g : W_o);
        const float* b = gate == 0 ? b_f : (gate == 1 ? b_g : b_o);
        for (int kk = 0; kk < 6; kk++) {
            const float v = kk < DD ? __ldg(&W[col * WROW + kk]) : __ldg(&b[col]);
            *(__half*)(smem + OFF_BHI + n * ROWB + (256 + kk) * 2) = __float2half_rn(v);
        }
    }
    if (tid < BT)
        *(__half*)(smem + OFF_AHI + tid * ROWB + 261 * 2) = __float2half_rn(1.0f);
    if (tid < BT) {
        const float* xp = x_dyn + (size_t)(row0 + tid) * TT * DD;
#pragma unroll
        for (int d = 0; d < DD; d++) xs[tid * DD + d] = __ldg(xp + d);
    }

    // ---- MMA warp geometry: 8 warps = 4 row-groups x 2 col-groups (48 cols) ----
    const int rg  = wid >> 1;
    const int cg  = wid & 1;
    const int tg  = lane >> 2;
    const int tig = lane & 3;

    const uint32_t aOff = (uint32_t)((rg * 16 + (lane & 15)) * ROWB + (lane >> 4) * 16);
    const uint32_t aHiA = sAHI + aOff;
    const uint32_t aLoA = sALO + aOff;
    uint32_t bHiA[3];
#pragma unroll
    for (int p = 0; p < 3; p++) {
        const uint32_t bOff =
            (uint32_t)((cg * 48 + p * 16 + ((lane >> 4) * 8) + (lane & 7)) * ROWB +
                       ((lane & 8) ? 16 : 0));
        bHiA[p] = sBHI + bOff;
    }

    // ---- per-lane cell state: rows {er0, er0+8}, cols {ecb..ecb+3} (global) ----
    const int er0 = rg * 16 + tg;
    const int ecb = col0 + cg * 16 + tig * 4;
    float ig[8], cs[8];
#pragma unroll
    for (int z = 0; z < 2; z++)
#pragma unroll
        for (int a = 0; a < 4; a++) {
            const int r = row0 + er0 + z * 8;
            const int c = ecb + a;
            float s = __ldg(&b_i[c]);
            for (int ss = 0; ss < SS; ss++)
                s = fmaf(__ldg(&x_stat[r * SS + ss]), __ldg(&W_i[c * SS + ss]), s);
            ig[z * 4 + a] = sigmoid_precise(s);   // one-time: keep full precision
            cs[z * 4 + a] = 0.f;
        }
    __syncthreads();

    const int ks0 = 2 * cj, ks1 = 2 * cj + 1;    // own k-steps (self-staged)

    // ---- recurrence ----
    for (int t = 0; t < TT; t++) {
        // x(t) -> A x-region (hi/lo)
        if (tid < BT) {
            const float* xr = xs + (t & 1) * 320 + tid * DD;
#pragma unroll
            for (int d = 0; d < DD; d++) {
                const float v = xr[d];
                const __half vh = __float2half_rn(v);
                const __half vl = __float2half_rn((v - __half2float(vh)) * LO_SCALE);
                *(__half*)(smem + OFF_AHI + tid * ROWB + (256 + d) * 2) = vh;
                *(__half*)(smem + OFF_ALO + tid * ROWB + (256 + d) * 2) = vl;
            }
        }

        // ---- per-warp producer pipelining: warp w polls flag w, stages chunk w ----
        if (t > 0) {
            const int rb = (t - 1) & 1;
            if (wid != cj) {
                if (lane == 0) {
                    const volatile unsigned* fp = &g_flag[(bi * CPG + wid) * 32];
                    while (*fp < (unsigned)t) {}
                }
                __syncwarp();
#pragma unroll
                for (int i = 0; i < 8; i++) {
                    const int e = lane + 32 * i;          // 0..255
                    const int r = e >> 2, u = e & 3;
                    const int unit = (wid << 2) + u;
                    const uint32_t d = (uint32_t)(r * ROWB + unit * 16);
                    cpa16(sAHI + d, (const char*)&g_hhi[rb][row0 + r][0] + unit * 16);
                    cpa16(sALO + d, (const char*)&g_hlo[rb][row0 + r][0] + unit * 16);
                }
            } else {
                // own chunk is self-staged; this warp prefetches x(t+1)
                const int tn = (t + 1 < TT) ? t + 1 : TT - 1;
                const uint32_t xb = sXS + (uint32_t)(((t + 1) & 1) * 320 * 4);
#pragma unroll
                for (int i = 0; i < 10; i++) {
                    const int e = lane + 32 * i;          // 0..319
                    const int r = e / 5, d = e - r * 5;
                    cpa4(xb + (uint32_t)e * 4,
                         &x_dyn[((size_t)(row0 + r) * TT + tn) * DD + d]);
                }
            }
            asm volatile("cp.async.commit_group;" ::: "memory");
        } else {
            const uint32_t xb = sXS + (uint32_t)(320 * 4);
            for (int e = tid; e < BT * DD; e += NTHR) {
                const int r = e / DD, d = e - r * DD;
                cpa4(xb + (uint32_t)e * 4, &x_dyn[((size_t)(row0 + r) * TT + 1) * DD + d]);
            }
            asm volatile("cp.async.commit_group;" ::: "memory");
        }
        __syncthreads();                                  // x-region visible

        float d1[6][4], d2[6][4];
#pragma unroll
        for (int q = 0; q < 6; q++)
#pragma unroll
            for (int v = 0; v < 4; v++) { d1[q][v] = 0.f; d2[q][v] = 0.f; }

#define DO_KSTEP(KS)                                                                   \
        {                                                                              \
            const uint32_t kb = (uint32_t)((KS) * 32);                                 \
            uint32_t ah0, ah1, ah2, ah3, al0, al1, al2, al3;                           \
            ldsm4(ah0, ah1, ah2, ah3, aHiA + kb);                                      \
            ldsm4(al0, al1, al2, al3, aLoA + kb);                                      \
            _Pragma("unroll")                                                          \
            for (int p = 0; p < 3; p++) {                                              \
                uint32_t bh0, bh1, bh2, bh3;                                           \
                ldsm4(bh0, bh1, bh2, bh3, bHiA[p] + kb);                               \
                mma16816(d1[p*2+0], ah0, ah1, ah2, ah3, bh0, bh1);                     \
                mma16816(d1[p*2+1], ah0, ah1, ah2, ah3, bh2, bh3);                     \
                mma16816(d2[p*2+0], al0, al1, al2, al3, bh0, bh1);                     \
                mma16816(d2[p*2+1], al0, al1, al2, al3, bh2, bh3);                     \
            }                                                                          \
        }

        // overlap the cp.async flight with x k-step + own two k-steps (self-staged)
        DO_KSTEP(16);
        DO_KSTEP(ks0);
        DO_KSTEP(ks1);
        asm volatile("cp.async.wait_group 0;" ::: "memory");
        __syncthreads();
#pragma unroll
        for (int ks = 0; ks < 16; ks++) {
            if ((ks >> 1) == cj) continue;       // own k-steps already done
            DO_KSTEP(ks);
        }

        // ---- in-register epilogue (HW tanh); publish h to global + own SMEM chunk ----
        const int wb = t & 1;
        __half hh[2][4], hl[2][4];
#pragma unroll
        for (int z = 0; z < 2; z++)
#pragma unroll
            for (int a = 0; a < 4; a++) {
                const int sf = 3 * a, sg = 3 * a + 1, so = 3 * a + 2;
                const float pf = fmaf(d2[sf >> 1][(z << 1) | (sf & 1)], LO_INV,
                                      d1[sf >> 1][(z << 1) | (sf & 1)]);
                const float pg = fmaf(d2[sg >> 1][(z << 1) | (sg & 1)], LO_INV,
                                      d1[sg >> 1][(z << 1) | (sg & 1)]);
                const float po = fmaf(d2[so >> 1][(z << 1) | (so & 1)], LO_INV,
                                      d1[so >> 1][(z << 1) | (so & 1)]);
                const float f = sigmoid_fast(pf);
                const float g = tanh_fast(pg);
                const float o = sigmoid_fast(po);
                const float cn = fmaf(f, cs[z * 4 + a], ig[z * 4 + a] * g);
                cs[z * 4 + a] = cn;
                const float hv = o * tanh_fast(cn);
                hh[z][a] = __float2half_rn(hv);
                hl[z][a] = __float2half_rn((hv - __half2float(hh[z][a])) * LO_SCALE);
            }
        *(uint2*)&g_hhi[wb][row0 + er0][ecb]     = *(uint2*)hh[0];
        *(uint2*)&g_hhi[wb][row0 + er0 + 8][ecb] = *(uint2*)hh[1];
        *(uint2*)&g_hlo[wb][row0 + er0][ecb]     = *(uint2*)hl[0];
        *(uint2*)&g_hlo[wb][row0 + er0 + 8][ecb] = *(uint2*)hl[1];
        // self-stage own chunk for next step (skips the global round-trip)
        *(uint2*)(smem + OFF_AHI + er0 * ROWB + ecb * 2)       = *(uint2*)hh[0];
        *(uint2*)(smem + OFF_AHI + (er0 + 8) * ROWB + ecb * 2) = *(uint2*)hh[1];
        *(uint2*)(smem + OFF_ALO + er0 * ROWB + ecb * 2)       = *(uint2*)hl[0];
        *(uint2*)(smem + OFF_ALO + (er0 + 8) * ROWB + ecb * 2) = *(uint2*)hl[1];

        __syncthreads();
        if (tid == 0) {
            // release-reduction: publishes all CTA stores (ordered by syncthreads)
            asm volatile("red.release.gpu.global.add.u32 [%0], %1;"
                         :: "l"(&g_flag[(bi * CPG + cj) * 32]), "r"(1u) : "memory");
        }
    }

    // ---- head (cj == 0): out[b] = h_T . W_head + b_head ----
    if (cj == 0) {
        if (tid < CPG) {
            const volatile unsigned* fp = &g_flag[(bi * CPG + tid) * 32];
            while (*fp < (unsigned)TT) __nanosleep(32);
        }
        __syncthreads();
        const int row = tid >> 2, part = tid & 3;
        const int r = row0 + row;
        const int rb = (TT - 1) & 1;
        float s = 0.f;
        for (int k = part * 64; k < part * 64 + 64; k++) {
            const float hv = __half2float(__ldcg(&g_hhi[rb][r][k])) +
                             __half2float(__ldcg(&g_hlo[rb][r][k])) * LO_INV;
            s = fmaf(hv, __ldg(&W_head[k]), s);
        }
        s += __shfl_xor_sync(0xffffffffu, s, 1);
        s += __shfl_xor_sync(0xffffffffu, s, 2);
        if (part == 0) out[r] = s + __ldg(&b_head[0]);
    }

    // ---- reset flags for deterministic graph replay ----
    __syncthreads();
    if (tid == 0) {
        __threadfence();
        atomicAdd(&g_done[bi * 32], 1u);
        if (cj == 0) {
            while (atomicAdd(&g_done[bi * 32], 0u) < CPG) __nanosleep(64);
            for (int s = 0; s < CPG; s++)
                atomicExch(&g_flag[(bi * CPG + s) * 32], 0u);
            atomicExch(&g_done[bi * 32], 0u);
        }
    }
}

extern "C" void kernel_launch(void* const* d_in, const int* in_sizes, int n_in,
                              void* d_out, int out_size) {
    (void)in_sizes; (void)n_in; (void)out_size;
    cudaFuncSetAttribute(ealstm_kernel,
                         cudaFuncAttributeMaxDynamicSharedMemorySize, SMEM_SZ);
    ealstm_kernel<<<NCTA, NTHR, SMEM_SZ>>>(
        (const float*)d_in[0],  (const float*)d_in[1],
        (const float*)d_in[2],  (const float*)d_in[3],
        (const float*)d_in[4],  (const float*)d_in[5],
        (const float*)d_in[6],  (const float*)d_in[7],
        (const float*)d_in[8],  (const float*)d_in[9],
        (const float*)d_in[10], (const float*)d_in[11],
        (float*)d_out);
}